// round 1
// baseline (speedup 1.0000x reference)
#include <cuda_runtime.h>
#include <stdint.h>

#define BB 4
#define NN 4096
#define DD 128
#define KK 2048
#define EPSV 1e-10f

// ---- scratch (no allocation allowed) ----
__device__ unsigned long long d_keys[BB * NN];   // 128 KB
__device__ int   d_idx[BB * KK];
__device__ float d_vals[BB * KK];
__device__ int   d_colsrc[BB * KK];              // selected columns, ascending
__device__ int   d_dest[BB * KK];                // their destination j (score order)

// output layout: g_new | new_h | idx (float32)
#define OFF_G 0
#define OFF_H ((size_t)BB * KK * KK)
#define OFF_I (OFF_H + (size_t)BB * KK * DD)

// ---------------------------------------------------------------------------
// Kernel 1: scores = sigmoid(h . w + b), packed into sortable u64 keys.
// key = (score_bits << 32) | (0xFFFFFFFF - node)  -> descending sort gives
// descending score, ascending index on ties (jax.lax.top_k semantics).
// One warp per node.
// ---------------------------------------------------------------------------
__global__ void scores_kernel(const float* __restrict__ h,
                              const float* __restrict__ w,
                              const float* __restrict__ bptr) {
    int gwarp = (blockIdx.x * blockDim.x + threadIdx.x) >> 5;
    int lane  = threadIdx.x & 31;
    if (gwarp >= BB * NN) return;
    const float* hrow = h + (size_t)gwarp * DD;
    float s = 0.f;
    #pragma unroll
    for (int d = lane; d < DD; d += 32) s += hrow[d] * w[d];
    #pragma unroll
    for (int o = 16; o; o >>= 1) s += __shfl_xor_sync(0xFFFFFFFFu, s, o);
    if (lane == 0) {
        float x  = s + bptr[0];
        float sc = 1.0f / (1.0f + expf(-x));          // in (0,1): bits monotone
        unsigned int sb = __float_as_uint(sc);
        unsigned int node = (unsigned int)(gwarp & (NN - 1));
        d_keys[gwarp] = ((unsigned long long)sb << 32) |
                        (unsigned long long)(0xFFFFFFFFu - node);
    }
}

// ---------------------------------------------------------------------------
// Kernel 2: per-batch full bitonic sort (descending) of 4096 keys in smem,
// emit top-K idx/vals, then bitonic-sort (ascending) the K (col, j) pairs
// so the gather kernel can read columns in ascending order.
// One block per batch, 1024 threads, 32 KB smem.
// ---------------------------------------------------------------------------
__global__ void sort_kernel() {
    __shared__ unsigned long long sk[NN];
    const int b = blockIdx.x, tid = threadIdx.x;

    for (int i = tid; i < NN; i += 1024) sk[i] = d_keys[b * NN + i];
    __syncthreads();

    // bitonic sort DESCENDING
    for (int k = 2; k <= NN; k <<= 1) {
        for (int j = k >> 1; j > 0; j >>= 1) {
            for (int i = tid; i < NN; i += 1024) {
                int l = i ^ j;
                if (l > i) {
                    unsigned long long a = sk[i], c = sk[l];
                    bool up = ((i & k) == 0);             // up-block: descending
                    if (up ? (a < c) : (a > c)) { sk[i] = c; sk[l] = a; }
                }
            }
            __syncthreads();
        }
    }

    // emit top-K and build (col<<32 | j) keys in registers
    unsigned long long ck[2];
    int cnt = 0;
    for (int i = tid; i < KK; i += 1024) {
        unsigned long long key = sk[i];
        unsigned int node = 0xFFFFFFFFu - (unsigned int)(key & 0xFFFFFFFFu);
        d_idx [b * KK + i] = (int)node;
        d_vals[b * KK + i] = __uint_as_float((unsigned int)(key >> 32));
        ck[cnt++] = ((unsigned long long)node << 32) | (unsigned int)i;
    }
    __syncthreads();
    cnt = 0;
    for (int i = tid; i < KK; i += 1024) sk[i] = ck[cnt++];
    __syncthreads();

    // bitonic sort ASCENDING on K entries
    for (int k = 2; k <= KK; k <<= 1) {
        for (int j = k >> 1; j > 0; j >>= 1) {
            for (int i = tid; i < KK; i += 1024) {
                int l = i ^ j;
                if (l > i) {
                    unsigned long long a = sk[i], c = sk[l];
                    bool up = ((i & k) == 0);             // up-block: ascending
                    if (up ? (a > c) : (a < c)) { sk[i] = c; sk[l] = a; }
                }
            }
            __syncthreads();
        }
    }
    for (int i = tid; i < KK; i += 1024) {
        unsigned long long key = sk[i];
        d_colsrc[b * KK + i] = (int)(key >> 32);
        d_dest  [b * KK + i] = (int)(key & 0xFFFFFFFFu);
    }
}

// ---------------------------------------------------------------------------
// Kernel 3: new_h = h[idx] * vals, plus idx (as float). One block per out row.
// ---------------------------------------------------------------------------
__global__ void newh_kernel(const float* __restrict__ h, float* __restrict__ out) {
    int row  = blockIdx.x;                 // 0 .. B*K-1
    int b    = row >> 11;                  // /K
    int node = d_idx[row];
    float v  = d_vals[row];
    const float* src = h + ((size_t)b * NN + node) * DD;
    float* dst = out + OFF_H + (size_t)row * DD;
    dst[threadIdx.x] = src[threadIdx.x] * v;
    if (threadIdx.x == 0) out[OFF_I + row] = (float)node;
}

// ---------------------------------------------------------------------------
// Kernel 4: gathered adjacency + degree normalize.
// One block per output row. Read source row columns in ASCENDING column order
// (near-coalesced), scatter to shared in score order, reduce for deg,
// coalesced write of svals * 1/(deg+eps).
// ---------------------------------------------------------------------------
__global__ void gatherg_kernel(const float* __restrict__ g, float* __restrict__ out) {
    __shared__ float svals[KK];            // 8 KB
    __shared__ float wsum[8];
    const int b = blockIdx.y, i = blockIdx.x, tid = threadIdx.x;
    const int node = d_idx[b * KK + i];
    const float* grow = g + ((size_t)b * NN + node) * NN;
    const int* cs = d_colsrc + b * KK;
    const int* de = d_dest   + b * KK;

    float local = 0.f;
    #pragma unroll 4
    for (int j = tid; j < KK; j += 256) {
        float v = __ldg(grow + cs[j]);
        svals[de[j]] = v;
        local += v;
    }
    #pragma unroll
    for (int o = 16; o; o >>= 1) local += __shfl_xor_sync(0xFFFFFFFFu, local, o);
    if ((tid & 31) == 0) wsum[tid >> 5] = local;
    __syncthreads();                       // also orders svals scatter vs reads

    float deg = 0.f;
    #pragma unroll
    for (int wv = 0; wv < 8; wv++) deg += wsum[wv];
    float inv = 1.0f / (deg + EPSV);

    float* dst = out + OFF_G + ((size_t)(b * KK + i)) * KK;
    #pragma unroll 4
    for (int j = tid; j < KK; j += 256) dst[j] = svals[j] * inv;
}

// ---------------------------------------------------------------------------
extern "C" void kernel_launch(void* const* d_in, const int* in_sizes, int n_in,
                              void* d_out, int out_size) {
    const float* g = (const float*)d_in[0];   // [B,N,N]
    const float* h = (const float*)d_in[1];   // [B,N,D]
    const float* w = (const float*)d_in[2];   // [D]
    const float* b = (const float*)d_in[3];   // scalar
    float* out = (float*)d_out;

    // 1) scores: one warp per node, 128-thread blocks -> 4 nodes/block
    scores_kernel<<<(BB * NN) / 4, 128>>>(h, w, b);
    // 2) per-batch sort + column re-sort
    sort_kernel<<<BB, 1024>>>();
    // 3) new_h + idx
    newh_kernel<<<BB * KK, DD>>>(h, out);
    // 4) gathered adjacency
    dim3 grid(KK, BB);
    gatherg_kernel<<<grid, 256>>>(g, out);
}

// round 2
// speedup vs baseline: 1.3756x; 1.3756x over previous
#include <cuda_runtime.h>
#include <stdint.h>

#define BB 4
#define NN 4096
#define DD 128
#define KK 2048
#define EPSV 1e-10f

// ---- scratch (no allocation allowed) ----
__device__ unsigned long long d_keys[BB * NN];   // 128 KB
__device__ int   d_idx[BB * KK];
__device__ float d_vals[BB * KK];

// output layout: g_new | new_h | idx (float32)
#define OFF_G 0
#define OFF_H ((size_t)BB * KK * KK)
#define OFF_I (OFF_H + (size_t)BB * KK * DD)

// ---------------------------------------------------------------------------
// Kernel 1: scores = sigmoid(h . w + b), packed into sortable u64 keys.
// key = (score_bits << 32) | (0xFFFFFFFF - node). Higher key = higher score,
// ties -> smaller node index (jax.lax.top_k semantics). Scores in (0,1) so
// float bits are monotone. One warp per node.
// ---------------------------------------------------------------------------
__global__ void scores_kernel(const float* __restrict__ h,
                              const float* __restrict__ w,
                              const float* __restrict__ bptr) {
    int gwarp = (blockIdx.x * blockDim.x + threadIdx.x) >> 5;
    int lane  = threadIdx.x & 31;
    if (gwarp >= BB * NN) return;
    const float* hrow = h + (size_t)gwarp * DD;
    float s = 0.f;
    #pragma unroll
    for (int d = lane; d < DD; d += 32) s += hrow[d] * w[d];
    #pragma unroll
    for (int o = 16; o; o >>= 1) s += __shfl_xor_sync(0xFFFFFFFFu, s, o);
    if (lane == 0) {
        float x  = s + bptr[0];
        float sc = 1.0f / (1.0f + expf(-x));
        unsigned int sb = __float_as_uint(sc);
        unsigned int node = (unsigned int)(gwarp & (NN - 1));
        d_keys[gwarp] = ((unsigned long long)sb << 32) |
                        (unsigned long long)(0xFFFFFFFFu - node);
    }
}

// ---------------------------------------------------------------------------
// Kernel 2: exact rank by counting (keys are unique). Each block loads the
// batch's 4096 keys into smem; each thread ranks ONE node via a uniform
// (broadcast) scan over all keys, then scatters into score order.
// 16 blocks/batch x 256 threads. Replaces the serial bitonic sorts.
// ---------------------------------------------------------------------------
#define RBLK 16   // blocks per batch
__global__ void rank_kernel() {
    __shared__ unsigned long long sk[NN];          // 32 KB
    const int b    = blockIdx.x / RBLK;
    const int blk  = blockIdx.x % RBLK;
    const int tid  = threadIdx.x;
    for (int i = tid; i < NN; i += 256) sk[i] = d_keys[b * NN + i];
    __syncthreads();

    const int node = blk * 256 + tid;
    const unsigned long long mykey = sk[node];
    int r = 0;
    #pragma unroll 16
    for (int i = 0; i < NN; i++) r += (sk[i] > mykey);
    if (r < KK) {
        d_idx [b * KK + r] = node;
        d_vals[b * KK + r] = __uint_as_float((unsigned int)(mykey >> 32));
    }
}

// ---------------------------------------------------------------------------
// Kernel 3: new_h = h[idx] * vals, plus idx (as float). One block per out row.
// ---------------------------------------------------------------------------
__global__ void newh_kernel(const float* __restrict__ h, float* __restrict__ out) {
    int row  = blockIdx.x;                 // 0 .. B*K-1
    int b    = row >> 11;
    int node = d_idx[row];
    float v  = d_vals[row];
    const float* src = h + ((size_t)b * NN + node) * DD;
    float* dst = out + OFF_H + (size_t)row * DD;
    dst[threadIdx.x] = src[threadIdx.x] * v;
    if (threadIdx.x == 0) out[OFF_I + row] = (float)node;
}

// ---------------------------------------------------------------------------
// Kernel 4: gathered adjacency + degree normalize.
// One block per output row. Stage the full 16KB source row into smem with
// coalesced float4 loads (same DRAM bytes, far fewer L1 wavefronts), pick the
// selected columns from smem, hold values in registers across the degree
// reduction, write coalesced.
// ---------------------------------------------------------------------------
__global__ void gatherg_kernel(const float* __restrict__ g, float* __restrict__ out) {
    __shared__ float srow[NN];             // 16 KB
    __shared__ float wsum[8];
    const int b = blockIdx.y, i = blockIdx.x, tid = threadIdx.x;
    const int node = d_idx[b * KK + i];

    // stage full row, coalesced
    const float4* src = (const float4*)(g + ((size_t)b * NN + node) * NN);
    float4* s4 = (float4*)srow;
    #pragma unroll
    for (int j = tid; j < NN / 4; j += 256) s4[j] = __ldg(src + j);

    // column indices (L2-hot, reused by all 2048 blocks of this batch)
    int   cidx[8];
    #pragma unroll
    for (int u = 0; u < 8; u++) cidx[u] = d_idx[b * KK + tid + 256 * u];
    __syncthreads();

    float v[8];
    float local = 0.f;
    #pragma unroll
    for (int u = 0; u < 8; u++) { v[u] = srow[cidx[u]]; local += v[u]; }
    #pragma unroll
    for (int o = 16; o; o >>= 1) local += __shfl_xor_sync(0xFFFFFFFFu, local, o);
    if ((tid & 31) == 0) wsum[tid >> 5] = local;
    __syncthreads();

    float deg = 0.f;
    #pragma unroll
    for (int wv = 0; wv < 8; wv++) deg += wsum[wv];
    const float inv = 1.0f / (deg + EPSV);

    float* dst = out + OFF_G + ((size_t)(b * KK + i)) * KK;
    #pragma unroll
    for (int u = 0; u < 8; u++) dst[tid + 256 * u] = v[u] * inv;
}

// ---------------------------------------------------------------------------
extern "C" void kernel_launch(void* const* d_in, const int* in_sizes, int n_in,
                              void* d_out, int out_size) {
    const float* g = (const float*)d_in[0];   // [B,N,N]
    const float* h = (const float*)d_in[1];   // [B,N,D]
    const float* w = (const float*)d_in[2];   // [D]
    const float* b = (const float*)d_in[3];   // scalar
    float* out = (float*)d_out;

    scores_kernel<<<(BB * NN) / 4, 128>>>(h, w, b);
    rank_kernel<<<BB * RBLK, 256>>>();
    newh_kernel<<<BB * KK, DD>>>(h, out);
    dim3 grid(KK, BB);
    gatherg_kernel<<<grid, 256>>>(g, out);
}

// round 3
// speedup vs baseline: 1.7447x; 1.2683x over previous
#include <cuda_runtime.h>
#include <stdint.h>

#define BB 4
#define NN 4096
#define DD 128
#define KK 2048
#define EPSV 1e-10f

// ---- scratch (no allocation allowed) ----
__device__ unsigned long long d_keys[BB * NN];   // 128 KB
__device__ int   d_idx[BB * KK];
__device__ float d_vals[BB * KK];

// output layout: g_new | new_h | idx (float32)
#define OFF_G 0
#define OFF_H ((size_t)BB * KK * KK)
#define OFF_I (OFF_H + (size_t)BB * KK * DD)

__device__ __forceinline__ unsigned smem_u32(const void* p) {
    unsigned a;
    asm("{ .reg .u64 t; cvta.to.shared.u64 t, %1; cvt.u32.u64 %0, t; }" : "=r"(a) : "l"(p));
    return a;
}

// ---------------------------------------------------------------------------
// Kernel 1: scores = sigmoid(h . w + b) packed into sortable u64 keys.
// key = (score_bits << 32) | (0xFFFFFFFF - node): descending key order ==
// descending score, ascending node on ties (jax.lax.top_k). One warp/node,
// float4 loads (32 lanes x float4 == 128 dims).
// ---------------------------------------------------------------------------
__global__ void scores_kernel(const float4* __restrict__ h,
                              const float4* __restrict__ w,
                              const float* __restrict__ bptr) {
    int gwarp = (blockIdx.x * blockDim.x + threadIdx.x) >> 5;
    int lane  = threadIdx.x & 31;
    if (gwarp >= BB * NN) return;
    float4 hv = h[(size_t)gwarp * (DD / 4) + lane];
    float4 wv = w[lane];
    float s = hv.x * wv.x + hv.y * wv.y + hv.z * wv.z + hv.w * wv.w;
    #pragma unroll
    for (int o = 16; o; o >>= 1) s += __shfl_xor_sync(0xFFFFFFFFu, s, o);
    if (lane == 0) {
        float x  = s + bptr[0];
        float sc = 1.0f / (1.0f + expf(-x));
        unsigned int sb = __float_as_uint(sc);
        unsigned int node = (unsigned int)(gwarp & (NN - 1));
        d_keys[gwarp] = ((unsigned long long)sb << 32) |
                        (unsigned long long)(0xFFFFFFFFu - node);
    }
}

// ---------------------------------------------------------------------------
// Kernel 2: exact rank-by-count (keys unique). 128 blocks x 128 threads =
// exactly one thread per node, 1 warp per SMSP across 128 SMs -> issue-
// parallel instead of issue-serialized. ulonglong2 smem reads.
// ---------------------------------------------------------------------------
__global__ void rank_kernel() {
    __shared__ __align__(16) unsigned long long sk[NN];   // 32 KB
    const int b   = blockIdx.x >> 5;       // 32 blocks per batch
    const int blk = blockIdx.x & 31;
    const int tid = threadIdx.x;           // 128 threads
    for (int i = tid; i < NN; i += 128) sk[i] = d_keys[b * NN + i];
    __syncthreads();

    const int node = blk * 128 + tid;
    const unsigned long long my = sk[node];
    const ulonglong2* sk2 = (const ulonglong2*)sk;
    int r = 0;
    #pragma unroll 8
    for (int i = 0; i < NN / 2; i++) {
        ulonglong2 kk = sk2[i];
        r += (kk.x > my) + (kk.y > my);
    }
    if (r < KK) {
        d_idx [b * KK + r] = node;
        d_vals[b * KK + r] = __uint_as_float((unsigned int)(my >> 32));
    }
}

// ---------------------------------------------------------------------------
// Kernel 3: gathered adjacency + degree normalize, FUSED with new_h and idx.
// One block per output row (b,i). The 16KB source row is staged into smem by
// a single cp.async.bulk (TMA path: no per-thread loads, no L1 wavefront
// storm). Columns picked from smem; 8 consecutive j per thread so writes are
// 2x STG.128 per thread, fully coalesced.
// ---------------------------------------------------------------------------
__global__ void gatherg_kernel(const float* __restrict__ g,
                               const float* __restrict__ h,
                               float* __restrict__ out) {
    __shared__ __align__(16) float srow[NN];               // 16 KB
    __shared__ float wsum[8];
    __shared__ __align__(8) unsigned long long mbar;

    const int b = blockIdx.y, i = blockIdx.x, tid = threadIdx.x;
    const int row  = b * KK + i;
    const int node = d_idx[row];
    const float v  = d_vals[row];

    const unsigned s_row  = smem_u32(srow);
    const unsigned s_mbar = smem_u32(&mbar);
    const float* grow = g + ((size_t)b * NN + node) * NN;

    if (tid == 0) {
        asm volatile("mbarrier.init.shared.b64 [%0], 1;" :: "r"(s_mbar) : "memory");
        asm volatile("fence.proxy.async.shared::cta;" ::: "memory");
        asm volatile("mbarrier.arrive.expect_tx.shared.b64 _, [%0], %1;"
                     :: "r"(s_mbar), "r"(NN * 4) : "memory");
        asm volatile(
            "cp.async.bulk.shared::cluster.global.mbarrier::complete_tx::bytes "
            "[%0], [%1], %2, [%3];"
            :: "r"(s_row), "l"(grow), "r"(NN * 4), "r"(s_mbar) : "memory");
    }

    // overlap: fused new_h (32 lanes x float4 = full 128-dim row) + idx
    if (tid >= 32 && tid < 64) {
        int l = tid - 32;
        float4 hv = ((const float4*)(h + ((size_t)b * NN + node) * DD))[l];
        hv.x *= v; hv.y *= v; hv.z *= v; hv.w *= v;
        ((float4*)(out + OFF_H + (size_t)row * DD))[l] = hv;
    }
    if (tid == 64) out[OFF_I + row] = (float)node;

    // overlap: column indices (L2-hot), 8 consecutive per thread
    const int4* cp4 = (const int4*)(d_idx + b * KK);
    int4 c0 = cp4[tid * 2];
    int4 c1 = cp4[tid * 2 + 1];

    __syncthreads();   // mbarrier init visible to all waiters
    // wait for bulk copy (parity 0)
    {
        unsigned done;
        do {
            asm volatile(
                "{ .reg .pred p; "
                "mbarrier.try_wait.parity.acquire.cta.shared::cta.b64 p, [%1], 0, 0x989680; "
                "selp.b32 %0, 1, 0, p; }"
                : "=r"(done) : "r"(s_mbar) : "memory");
        } while (!done);
    }

    float vv[8];
    vv[0] = srow[c0.x]; vv[1] = srow[c0.y]; vv[2] = srow[c0.z]; vv[3] = srow[c0.w];
    vv[4] = srow[c1.x]; vv[5] = srow[c1.y]; vv[6] = srow[c1.z]; vv[7] = srow[c1.w];
    float local = (vv[0] + vv[1]) + (vv[2] + vv[3]) + ((vv[4] + vv[5]) + (vv[6] + vv[7]));
    #pragma unroll
    for (int o = 16; o; o >>= 1) local += __shfl_xor_sync(0xFFFFFFFFu, local, o);
    if ((tid & 31) == 0) wsum[tid >> 5] = local;
    __syncthreads();

    float deg = 0.f;
    #pragma unroll
    for (int wv = 0; wv < 8; wv++) deg += wsum[wv];
    const float inv = 1.0f / (deg + EPSV);

    float4* dst4 = (float4*)(out + OFF_G + (size_t)row * KK);
    float4 o0 = make_float4(vv[0] * inv, vv[1] * inv, vv[2] * inv, vv[3] * inv);
    float4 o1 = make_float4(vv[4] * inv, vv[5] * inv, vv[6] * inv, vv[7] * inv);
    dst4[tid * 2]     = o0;
    dst4[tid * 2 + 1] = o1;
}

// ---------------------------------------------------------------------------
extern "C" void kernel_launch(void* const* d_in, const int* in_sizes, int n_in,
                              void* d_out, int out_size) {
    const float* g = (const float*)d_in[0];   // [B,N,N]
    const float* h = (const float*)d_in[1];   // [B,N,D]
    const float* w = (const float*)d_in[2];   // [D]
    const float* b = (const float*)d_in[3];   // scalar
    float* out = (float*)d_out;

    scores_kernel<<<(BB * NN) / 4, 128>>>((const float4*)h, (const float4*)w, b);
    rank_kernel<<<BB * 32, 128>>>();
    dim3 grid(KK, BB);
    gatherg_kernel<<<grid, 256>>>(g, h, out);
}